// round 4
// baseline (speedup 1.0000x reference)
#include <cuda_runtime.h>
#include <math.h>

#define B_    2
#define S_    2048
#define HID_  2048
#define H_    16
#define HK_   4
#define D_    128
#define R_    64
#define QKV_N 3072
#define M_    (B_*S_)   // 4096

// ---------------- scratch (device globals: allocation-free) ----------------
__device__ float g_qkv[(size_t)M_ * QKV_N];          // 50 MB
__device__ float g_q[(size_t)B_*H_*S_*D_];           // 33.5 MB
__device__ float g_k[(size_t)B_*HK_*S_*D_];          // 8.4 MB
__device__ float g_v[(size_t)B_*HK_*S_*D_];          // 8.4 MB
__device__ float g_attn[(size_t)M_ * HID_];          // 33.5 MB

// ---------------- fp32 SGEMM, C[M,N] = A[M,K] * B[N,K]^T (both K-contig) ---
// 128x128 tile, 8-deep k-slabs, register double-buffered global loads.
__global__ __launch_bounds__(256) void sgemm_nt(
    const float* __restrict__ A, const float* __restrict__ Bm,
    float* __restrict__ C, int M, int N, int K)
{
    __shared__ float As[8][128];
    __shared__ float Bs[8][128];
    const int tid = threadIdx.x;
    const int lr  = tid >> 1;          // 0..127 (tile row for loads)
    const int lc  = (tid & 1) << 2;    // 0 or 4
    const int tx  = tid & 15;
    const int ty  = tid >> 4;

    const float* Ap = A  + ((size_t)blockIdx.y * 128 + lr) * K + lc;
    const float* Bp = Bm + ((size_t)blockIdx.x * 128 + lr) * K + lc;

    float acc[8][8];
    #pragma unroll
    for (int i = 0; i < 8; i++)
        #pragma unroll
        for (int j = 0; j < 8; j++) acc[i][j] = 0.f;

    // prefetch first slab into registers
    float4 a4 = *(const float4*)(Ap);
    float4 b4 = *(const float4*)(Bp);

    for (int k0 = 0; k0 < K; k0 += 8) {
        // stage current slab to smem
        As[lc+0][lr] = a4.x; As[lc+1][lr] = a4.y;
        As[lc+2][lr] = a4.z; As[lc+3][lr] = a4.w;
        Bs[lc+0][lr] = b4.x; Bs[lc+1][lr] = b4.y;
        Bs[lc+2][lr] = b4.z; Bs[lc+3][lr] = b4.w;
        __syncthreads();

        // prefetch next slab (overlaps with FMA block below)
        if (k0 + 8 < K) {
            a4 = *(const float4*)(Ap + k0 + 8);
            b4 = *(const float4*)(Bp + k0 + 8);
        }

        #pragma unroll
        for (int k = 0; k < 8; k++) {
            float ar[8], br[8];
            *(float4*)&ar[0] = *(const float4*)&As[k][ty*8];
            *(float4*)&ar[4] = *(const float4*)&As[k][ty*8 + 4];
            *(float4*)&br[0] = *(const float4*)&Bs[k][tx*8];
            *(float4*)&br[4] = *(const float4*)&Bs[k][tx*8 + 4];
            #pragma unroll
            for (int i = 0; i < 8; i++)
                #pragma unroll
                for (int j = 0; j < 8; j++)
                    acc[i][j] += ar[i] * br[j];
        }
        __syncthreads();
    }

    float* Cp = C + ((size_t)blockIdx.y * 128 + ty*8) * N + blockIdx.x * 128 + tx*8;
    #pragma unroll
    for (int i = 0; i < 8; i++) {
        *(float4*)(Cp + (size_t)i * N)     = make_float4(acc[i][0], acc[i][1], acc[i][2], acc[i][3]);
        *(float4*)(Cp + (size_t)i * N + 4) = make_float4(acc[i][4], acc[i][5], acc[i][6], acc[i][7]);
    }
}

// ------------- fused per-head RMSNorm + RoPE + Q/K/V scatter ---------------
__global__ __launch_bounds__(128) void norm_rope_kernel(
    const float* __restrict__ qkv,
    const float* __restrict__ cosT, const float* __restrict__ sinT,
    const float* __restrict__ q_ln, const float* __restrict__ k_ln)
{
    const int head = blockIdx.x;   // 0..23
    const int s    = blockIdx.y;
    const int b    = blockIdx.z;
    const int d    = threadIdx.x;  // 0..127

    const float x = qkv[((size_t)(b*S_ + s)) * QKV_N + head*D_ + d];

    __shared__ float red[4];
    __shared__ float sh[128];

    float v = x * x;
    #pragma unroll
    for (int o = 16; o > 0; o >>= 1) v += __shfl_xor_sync(0xffffffffu, v, o);
    if ((d & 31) == 0) red[d >> 5] = v;
    __syncthreads();

    if (head < H_ + HK_) {   // q or k: norm + rope
        const float var = (red[0] + red[1] + red[2] + red[3]) * (1.0f / 128.0f);
        const float inv = rsqrtf(var + 1e-6f);
        const float* w  = (head < H_) ? q_ln : k_ln;
        const float y   = w[d] * x * inv;
        sh[d] = y;
        __syncthreads();

        float outv;
        if (d < R_) {
            const float c  = cosT[((size_t)(b*S_ + s)) * R_ + d];
            const float sn = sinT[((size_t)(b*S_ + s)) * R_ + d];
            const float rot = (d < R_/2) ? -sh[d + R_/2] : sh[d - R_/2];
            outv = y * c + rot * sn;
        } else {
            outv = y;
        }

        if (head < H_)
            g_q[(((size_t)(b*H_ + head)) * S_ + s) * D_ + d] = outv;
        else
            g_k[(((size_t)(b*HK_ + (head - H_))) * S_ + s) * D_ + d] = outv;
    } else {                 // v: raw copy
        g_v[(((size_t)(b*HK_ + (head - H_ - HK_))) * S_ + s) * D_ + d] = x;
    }
}

// ----------------------- fp32 flash attention (GQA) ------------------------
// Block: 256 threads, BM=64 query rows (4 threads/row splitting D=128 into 32-chunks),
// BN=32 KV rows staged in smem per iteration.
__global__ __launch_bounds__(256) void flash_kernel()
{
    constexpr int BM = 64, BN = 32;
    __shared__ float Ks[BN][D_];
    __shared__ float Vs[BN][D_];

    const int tid  = threadIdx.x;
    const int bh   = blockIdx.y;          // 0..B*H-1
    const int b    = bh / H_;
    const int h    = bh % H_;
    const int hk   = h / (H_ / HK_);
    const int row  = tid >> 2;            // 0..63
    const int quad = tid & 3;
    const int cb   = quad * 32;

    const size_t qrow  = (size_t)blockIdx.x * BM + row;
    const float* qp    = g_q + (((size_t)(b*H_ + h)) * S_ + qrow) * D_ + cb;
    const float* kbase = g_k + ((size_t)(b*HK_ + hk)) * S_ * D_;
    const float* vbase = g_v + ((size_t)(b*HK_ + hk)) * S_ * D_;

    float4 qreg[8];
    #pragma unroll
    for (int i = 0; i < 8; i++) qreg[i] = *(const float4*)(qp + i*4);

    float o[32];
    #pragma unroll
    for (int i = 0; i < 32; i++) o[i] = 0.f;
    float m = -1e30f, l = 0.f;
    const float scale = 0.08838834764831845f;  // 1/sqrt(128)

    for (int kb = 0; kb < S_; kb += BN) {
        // stage K/V tiles (coalesced float4)
        const float4* ksrc = (const float4*)(kbase + (size_t)kb * D_);
        const float4* vsrc = (const float4*)(vbase + (size_t)kb * D_);
        float4* kdst = (float4*)&Ks[0][0];
        float4* vdst = (float4*)&Vs[0][0];
        #pragma unroll
        for (int t = 0; t < (BN*D_/4)/256; t++) {
            kdst[tid + t*256] = ksrc[tid + t*256];
            vdst[tid + t*256] = vsrc[tid + t*256];
        }
        __syncthreads();

        float sreg[BN];
        #pragma unroll 4
        for (int j = 0; j < BN; j++) {
            float acc = 0.f;
            const float4* kp = (const float4*)&Ks[j][cb];
            #pragma unroll
            for (int i = 0; i < 8; i++) {
                float4 kk = kp[i];
                acc += qreg[i].x*kk.x + qreg[i].y*kk.y + qreg[i].z*kk.z + qreg[i].w*kk.w;
            }
            acc += __shfl_xor_sync(0xffffffffu, acc, 1);
            acc += __shfl_xor_sync(0xffffffffu, acc, 2);
            sreg[j] = acc * scale;
        }

        float tmax = -1e30f;
        #pragma unroll
        for (int j = 0; j < BN; j++) tmax = fmaxf(tmax, sreg[j]);
        const float mnew  = fmaxf(m, tmax);
        const float alpha = __expf(m - mnew);
        l *= alpha;
        #pragma unroll
        for (int i = 0; i < 32; i++) o[i] *= alpha;

        #pragma unroll 4
        for (int j = 0; j < BN; j++) {
            const float p = __expf(sreg[j] - mnew);
            l += p;
            const float4* vp = (const float4*)&Vs[j][cb];
            #pragma unroll
            for (int i = 0; i < 8; i++) {
                float4 vv = vp[i];
                o[4*i+0] += p * vv.x;
                o[4*i+1] += p * vv.y;
                o[4*i+2] += p * vv.z;
                o[4*i+3] += p * vv.w;
            }
        }
        m = mnew;
        __syncthreads();
    }

    const float invl = 1.0f / l;
    float* op = g_attn + ((size_t)b * S_ + qrow) * HID_ + h*D_ + cb;
    #pragma unroll
    for (int i = 0; i < 8; i++)
        ((float4*)op)[i] = make_float4(o[4*i]*invl, o[4*i+1]*invl,
                                       o[4*i+2]*invl, o[4*i+3]*invl);
}

// ------------------------------- launch ------------------------------------
extern "C" void kernel_launch(void* const* d_in, const int* in_sizes, int n_in,
                              void* d_out, int out_size)
{
    const float* hidden  = (const float*)d_in[0];
    const float* cosT    = (const float*)d_in[1];
    const float* sinT    = (const float*)d_in[2];
    const float* w_qkv   = (const float*)d_in[3];
    const float* q_ln    = (const float*)d_in[4];
    const float* k_ln    = (const float*)d_in[5];
    const float* w_dense = (const float*)d_in[6];
    float* out = (float*)d_out;

    float *qkv_ptr, *attn_ptr;
    cudaGetSymbolAddress((void**)&qkv_ptr,  g_qkv);
    cudaGetSymbolAddress((void**)&attn_ptr, g_attn);

    // 1) QKV projection: [4096,2048] x [3072,2048]^T -> [4096,3072]
    {
        dim3 grid(QKV_N/128, M_/128);
        sgemm_nt<<<grid, 256>>>(hidden, w_qkv, qkv_ptr, M_, QKV_N, HID_);
    }
    // 2) RMSNorm + RoPE + scatter to q/k/v
    {
        dim3 grid(H_ + 2*HK_, S_, B_);
        norm_rope_kernel<<<grid, 128>>>(qkv_ptr, cosT, sinT, q_ln, k_ln);
    }
    // 3) Flash attention
    {
        dim3 grid(S_/64, B_*H_);
        flash_kernel<<<grid, 256>>>();
    }
    // 4) Output projection: [4096,2048] x [2048,2048]^T -> [4096,2048]
    {
        dim3 grid(HID_/128, M_/128);
        sgemm_nt<<<grid, 256>>>(attn_ptr, w_dense, out, M_, HID_, HID_);
    }
}

// round 6
// speedup vs baseline: 1.0870x; 1.0870x over previous
#include <cuda_runtime.h>
#include <math.h>
#include <stdint.h>

#define B_    2
#define S_    2048
#define HID_  2048
#define H_    16
#define HK_   4
#define D_    128
#define R_    64
#define QKV_N 3072
#define M_    (B_*S_)   // 4096

// ---------------- scratch (device globals: allocation-free) ----------------
__device__ float g_qkv[(size_t)M_ * QKV_N];
__device__ float g_q[(size_t)B_*H_*S_*D_];
__device__ float g_k[(size_t)B_*HK_*S_*D_];
__device__ float g_v[(size_t)B_*HK_*S_*D_];
__device__ float g_attn[(size_t)M_ * HID_];

// ---------------------------------------------------------------------------
// tf32 helpers
// ---------------------------------------------------------------------------
__device__ __forceinline__ float to_tf32(float x) {
    uint32_t u;
    asm("cvt.rna.tf32.f32 %0, %1;" : "=r"(u) : "f"(x));
    return __uint_as_float(u);
}

__device__ __forceinline__ void mma_tf32(float* d, const uint32_t* a, const uint32_t* b) {
    asm volatile(
        "mma.sync.aligned.m16n8k8.row.col.f32.tf32.tf32.f32 "
        "{%0,%1,%2,%3}, {%4,%5,%6,%7}, {%8,%9}, {%0,%1,%2,%3};"
        : "+f"(d[0]), "+f"(d[1]), "+f"(d[2]), "+f"(d[3])
        : "r"(a[0]), "r"(a[1]), "r"(a[2]), "r"(a[3]), "r"(b[0]), "r"(b[1]));
}

// ---------------------------------------------------------------------------
// tf32 tensor-core GEMM: C[M,N] = A[M,K] * B[N,K]^T  (both K-contiguous)
// 128x128x16 block tile, 8 warps, each warp 64x32 via 4x4 m16n8k8 tiles.
// ---------------------------------------------------------------------------
#define GP 20   // smem row pitch (floats): conflict-free & float4-aligned

__global__ __launch_bounds__(256) void gemm_tf32_nt(
    const float* __restrict__ A, const float* __restrict__ Bm,
    float* __restrict__ C, int M, int N, int K)
{
    __shared__ float As[128][GP];
    __shared__ float Bs[128][GP];

    const int tid  = threadIdx.x;
    const int lane = tid & 31;
    const int warp = tid >> 5;
    const int wm   = (warp >> 2) * 64;   // warp m-offset within tile (0/64)
    const int wn   = (warp & 3) * 32;    // warp n-offset within tile (0..96)

    // staging mapping: each thread stages one row-half (8 floats) of A and B
    const int srow = tid >> 1;           // 0..127
    const int skc  = (tid & 1) * 8;      // 0 or 8

    const float* Ap = A  + ((size_t)blockIdx.y * 128 + srow) * K + skc;
    const float* Bp = Bm + ((size_t)blockIdx.x * 128 + srow) * K + skc;

    float acc[4][4][4];
    #pragma unroll
    for (int i = 0; i < 4; i++)
        #pragma unroll
        for (int j = 0; j < 4; j++)
            #pragma unroll
            for (int r = 0; r < 4; r++) acc[i][j][r] = 0.f;

    // prefetch first slab
    float4 pa0 = *(const float4*)(Ap);
    float4 pa1 = *(const float4*)(Ap + 4);
    float4 pb0 = *(const float4*)(Bp);
    float4 pb1 = *(const float4*)(Bp + 4);

    const int tr = lane >> 2;   // 0..7
    const int tc = lane & 3;    // 0..3

    for (int k0 = 0; k0 < K; k0 += 16) {
        // stage (tf32-rounded once here; numerically identical to rounding in mma)
        *(float4*)&As[srow][skc]     = make_float4(to_tf32(pa0.x), to_tf32(pa0.y), to_tf32(pa0.z), to_tf32(pa0.w));
        *(float4*)&As[srow][skc + 4] = make_float4(to_tf32(pa1.x), to_tf32(pa1.y), to_tf32(pa1.z), to_tf32(pa1.w));
        *(float4*)&Bs[srow][skc]     = make_float4(to_tf32(pb0.x), to_tf32(pb0.y), to_tf32(pb0.z), to_tf32(pb0.w));
        *(float4*)&Bs[srow][skc + 4] = make_float4(to_tf32(pb1.x), to_tf32(pb1.y), to_tf32(pb1.z), to_tf32(pb1.w));
        __syncthreads();

        if (k0 + 16 < K) {   // prefetch next slab (overlaps with mma block)
            pa0 = *(const float4*)(Ap + k0 + 16);
            pa1 = *(const float4*)(Ap + k0 + 20);
            pb0 = *(const float4*)(Bp + k0 + 16);
            pb1 = *(const float4*)(Bp + k0 + 20);
        }

        #pragma unroll
        for (int ks = 0; ks < 16; ks += 8) {
            uint32_t af[4][4], bf[4][2];
            #pragma unroll
            for (int mt = 0; mt < 4; mt++) {
                const int r0 = wm + mt * 16 + tr;
                af[mt][0] = __float_as_uint(As[r0    ][ks + tc    ]);
                af[mt][1] = __float_as_uint(As[r0 + 8][ks + tc    ]);
                af[mt][2] = __float_as_uint(As[r0    ][ks + tc + 4]);
                af[mt][3] = __float_as_uint(As[r0 + 8][ks + tc + 4]);
            }
            #pragma unroll
            for (int nt = 0; nt < 4; nt++) {
                const int c0 = wn + nt * 8 + tr;
                bf[nt][0] = __float_as_uint(Bs[c0][ks + tc    ]);
                bf[nt][1] = __float_as_uint(Bs[c0][ks + tc + 4]);
            }
            #pragma unroll
            for (int mt = 0; mt < 4; mt++)
                #pragma unroll
                for (int nt = 0; nt < 4; nt++)
                    mma_tf32(acc[mt][nt], af[mt], bf[nt]);
        }
        __syncthreads();
    }

    // epilogue: c0/c1 at (row, 2c), (row, 2c+1); c2/c3 at row+8
    const int crow = (int)blockIdx.y * 128 + wm + tr;
    const int ccol = (int)blockIdx.x * 128 + wn + 2 * tc;
    #pragma unroll
    for (int mt = 0; mt < 4; mt++) {
        #pragma unroll
        for (int nt = 0; nt < 4; nt++) {
            float* Cp = C + (size_t)(crow + mt * 16) * N + ccol + nt * 8;
            *(float2*)Cp               = make_float2(acc[mt][nt][0], acc[mt][nt][1]);
            *(float2*)(Cp + 8 * (size_t)N) = make_float2(acc[mt][nt][2], acc[mt][nt][3]);
        }
    }
}

// ------------- fused per-head RMSNorm + RoPE + Q/K/V scatter ---------------
__global__ __launch_bounds__(128) void norm_rope_kernel(
    const float* __restrict__ qkv,
    const float* __restrict__ cosT, const float* __restrict__ sinT,
    const float* __restrict__ q_ln, const float* __restrict__ k_ln)
{
    const int head = blockIdx.x;   // 0..23
    const int s    = blockIdx.y;
    const int b    = blockIdx.z;
    const int d    = threadIdx.x;  // 0..127

    const float x = qkv[((size_t)(b*S_ + s)) * QKV_N + head*D_ + d];

    __shared__ float red[4];
    __shared__ float sh[128];

    float v = x * x;
    #pragma unroll
    for (int o = 16; o > 0; o >>= 1) v += __shfl_xor_sync(0xffffffffu, v, o);
    if ((d & 31) == 0) red[d >> 5] = v;
    __syncthreads();

    if (head < H_ + HK_) {   // q or k: norm + rope
        const float var = (red[0] + red[1] + red[2] + red[3]) * (1.0f / 128.0f);
        const float inv = rsqrtf(var + 1e-6f);
        const float* w  = (head < H_) ? q_ln : k_ln;
        const float y   = w[d] * x * inv;
        sh[d] = y;
        __syncthreads();

        float outv;
        if (d < R_) {
            const float c  = cosT[((size_t)(b*S_ + s)) * R_ + d];
            const float sn = sinT[((size_t)(b*S_ + s)) * R_ + d];
            const float rot = (d < R_/2) ? -sh[d + R_/2] : sh[d - R_/2];
            outv = y * c + rot * sn;
        } else {
            outv = y;
        }

        if (head < H_)
            g_q[(((size_t)(b*H_ + head)) * S_ + s) * D_ + d] = outv;
        else
            g_k[(((size_t)(b*HK_ + (head - H_))) * S_ + s) * D_ + d] = outv;
    } else {                 // v: raw copy
        g_v[(((size_t)(b*HK_ + (head - H_ - HK_))) * S_ + s) * D_ + d] = x;
    }
}

// ----------------------- fp32 flash attention (GQA) ------------------------
// BM=64 rows/block, 4 threads per row (32-dim chunks), BN=16 KV rows/iter.
// ALL j-loops fully unrolled so sreg stays register-resident (the round-4
// version's partial unroll demoted sreg[] to local memory).
__global__ __launch_bounds__(256) void flash_kernel()
{
    constexpr int BM = 64, BN = 16;
    __shared__ float Ks[BN][D_];
    __shared__ float Vs[BN][D_];

    const int tid  = threadIdx.x;
    const int bh   = blockIdx.y;          // 0..B*H-1
    const int b    = bh / H_;
    const int h    = bh % H_;
    const int hk   = h / (H_ / HK_);
    const int row  = tid >> 2;            // 0..63
    const int quad = tid & 3;
    const int cb   = quad * 32;

    const size_t qrow  = (size_t)blockIdx.x * BM + row;
    const float* qp    = g_q + (((size_t)(b*H_ + h)) * S_ + qrow) * D_ + cb;
    const float* kbase = g_k + ((size_t)(b*HK_ + hk)) * S_ * D_;
    const float* vbase = g_v + ((size_t)(b*HK_ + hk)) * S_ * D_;

    float4 qreg[8];
    #pragma unroll
    for (int i = 0; i < 8; i++) qreg[i] = *(const float4*)(qp + i*4);

    float o[32];
    #pragma unroll
    for (int i = 0; i < 32; i++) o[i] = 0.f;
    float m = -1e30f, l = 0.f;
    // scale * log2(e): run softmax in base-2 (exp2f = single MUFU.EX2)
    const float sc = 0.08838834764831845f * 1.4426950408889634f;

    for (int kb = 0; kb < S_; kb += BN) {
        // stage K/V tiles (coalesced float4): (16*128/4)/256 = 2 per array
        const float4* ksrc = (const float4*)(kbase + (size_t)kb * D_);
        const float4* vsrc = (const float4*)(vbase + (size_t)kb * D_);
        float4* kdst = (float4*)&Ks[0][0];
        float4* vdst = (float4*)&Vs[0][0];
        #pragma unroll
        for (int t = 0; t < 2; t++) {
            kdst[tid + t*256] = ksrc[tid + t*256];
            vdst[tid + t*256] = vsrc[tid + t*256];
        }
        __syncthreads();

        float sreg[BN];
        #pragma unroll
        for (int j = 0; j < BN; j++) {
            float a0 = 0.f, a1 = 0.f;   // split accumulators: shorter dep chain
            const float4* kp = (const float4*)&Ks[j][cb];
            #pragma unroll
            for (int i = 0; i < 8; i += 2) {
                float4 k0 = kp[i], k1 = kp[i+1];
                a0 += qreg[i].x*k0.x + qreg[i].y*k0.y + qreg[i].z*k0.z + qreg[i].w*k0.w;
                a1 += qreg[i+1].x*k1.x + qreg[i+1].y*k1.y + qreg[i+1].z*k1.z + qreg[i+1].w*k1.w;
            }
            float acc = a0 + a1;
            acc += __shfl_xor_sync(0xffffffffu, acc, 1);
            acc += __shfl_xor_sync(0xffffffffu, acc, 2);
            sreg[j] = acc * sc;
        }

        float tmax = sreg[0];
        #pragma unroll
        for (int j = 1; j < BN; j++) tmax = fmaxf(tmax, sreg[j]);
        const float mnew  = fmaxf(m, tmax);
        const float alpha = exp2f(m - mnew);
        l *= alpha;
        #pragma unroll
        for (int i = 0; i < 32; i++) o[i] *= alpha;

        #pragma unroll
        for (int j = 0; j < BN; j++) {
            const float p = exp2f(sreg[j] - mnew);
            l += p;
            const float4* vp = (const float4*)&Vs[j][cb];
            #pragma unroll
            for (int i = 0; i < 8; i++) {
                float4 vv = vp[i];
                o[4*i+0] += p * vv.x;
                o[4*i+1] += p * vv.y;
                o[4*i+2] += p * vv.z;
                o[4*i+3] += p * vv.w;
            }
        }
        m = mnew;
        __syncthreads();
    }

    const float invl = 1.0f / l;
    float* op = g_attn + ((size_t)b * S_ + qrow) * HID_ + h*D_ + cb;
    #pragma unroll
    for (int i = 0; i < 8; i++)
        ((float4*)op)[i] = make_float4(o[4*i]*invl, o[4*i+1]*invl,
                                       o[4*i+2]*invl, o[4*i+3]*invl);
}

// ------------------------------- launch ------------------------------------
extern "C" void kernel_launch(void* const* d_in, const int* in_sizes, int n_in,
                              void* d_out, int out_size)
{
    const float* hidden  = (const float*)d_in[0];
    const float* cosT    = (const float*)d_in[1];
    const float* sinT    = (const float*)d_in[2];
    const float* w_qkv   = (const float*)d_in[3];
    const float* q_ln    = (const float*)d_in[4];
    const float* k_ln    = (const float*)d_in[5];
    const float* w_dense = (const float*)d_in[6];
    float* out = (float*)d_out;

    float *qkv_ptr, *attn_ptr;
    cudaGetSymbolAddress((void**)&qkv_ptr,  g_qkv);
    cudaGetSymbolAddress((void**)&attn_ptr, g_attn);

    // 1) QKV projection: [4096,2048] x [3072,2048]^T -> [4096,3072]
    {
        dim3 grid(QKV_N/128, M_/128);
        gemm_tf32_nt<<<grid, 256>>>(hidden, w_qkv, qkv_ptr, M_, QKV_N, HID_);
    }
    // 2) RMSNorm + RoPE + scatter to q/k/v
    {
        dim3 grid(H_ + 2*HK_, S_, B_);
        norm_rope_kernel<<<grid, 128>>>(qkv_ptr, cosT, sinT, q_ln, k_ln);
    }
    // 3) Flash attention
    {
        dim3 grid(S_/64, B_*H_);
        flash_kernel<<<grid, 256>>>();
    }
    // 4) Output projection: [4096,2048] x [2048,2048]^T -> [4096,2048]
    {
        dim3 grid(HID_/128, M_/128);
        gemm_tf32_nt<<<grid, 256>>>(attn_ptr, w_dense, out, M_, HID_, HID_);
    }
}

// round 11
// speedup vs baseline: 4.7366x; 4.3574x over previous
#include <cuda_runtime.h>
#include <math.h>
#include <stdint.h>

#define B_    2
#define S_    2048
#define HID_  2048
#define H_    16
#define HK_   4
#define D_    128
#define R_    64
#define QKV_N 3072
#define M_    (B_*S_)   // 4096

// ---------------- scratch (device globals: allocation-free) ----------------
__device__ float g_qkv[(size_t)M_ * QKV_N];
__device__ float g_q[(size_t)B_*H_*S_*D_];
__device__ float g_k[(size_t)B_*HK_*S_*D_];
__device__ float g_v[(size_t)B_*HK_*S_*D_];
__device__ float g_attn[(size_t)M_ * HID_];

// ---------------------------------------------------------------------------
// tf32 helpers
// ---------------------------------------------------------------------------
__device__ __forceinline__ float to_tf32(float x) {
    uint32_t u;
    asm("cvt.rna.tf32.f32 %0, %1;" : "=r"(u) : "f"(x));
    return __uint_as_float(u);
}

__device__ __forceinline__ void mma_tf32(float* d, const uint32_t* a, const uint32_t* b) {
    asm volatile(
        "mma.sync.aligned.m16n8k8.row.col.f32.tf32.tf32.f32 "
        "{%0,%1,%2,%3}, {%4,%5,%6,%7}, {%8,%9}, {%0,%1,%2,%3};"
        : "+f"(d[0]), "+f"(d[1]), "+f"(d[2]), "+f"(d[3])
        : "r"(a[0]), "r"(a[1]), "r"(a[2]), "r"(a[3]), "r"(b[0]), "r"(b[1]));
}

// ---------------------------------------------------------------------------
// tf32 tensor-core GEMM: C[M,N] = A[M,K] * B[N,K]^T  (both K-contiguous)
// 128x128x16 block tile, 8 warps, each warp 64x32 via 4x4 m16n8k8 tiles.
// ---------------------------------------------------------------------------
#define GP 20   // smem row pitch (floats): conflict-free & float4-aligned

__global__ __launch_bounds__(256) void gemm_tf32_nt(
    const float* __restrict__ A, const float* __restrict__ Bm,
    float* __restrict__ C, int M, int N, int K)
{
    __shared__ float As[128][GP];
    __shared__ float Bs[128][GP];

    const int tid  = threadIdx.x;
    const int lane = tid & 31;
    const int warp = tid >> 5;
    const int wm   = (warp >> 2) * 64;
    const int wn   = (warp & 3) * 32;

    const int srow = tid >> 1;
    const int skc  = (tid & 1) * 8;

    const float* Ap = A  + ((size_t)blockIdx.y * 128 + srow) * K + skc;
    const float* Bp = Bm + ((size_t)blockIdx.x * 128 + srow) * K + skc;

    float acc[4][4][4];
    #pragma unroll
    for (int i = 0; i < 4; i++)
        #pragma unroll
        for (int j = 0; j < 4; j++)
            #pragma unroll
            for (int r = 0; r < 4; r++) acc[i][j][r] = 0.f;

    float4 pa0 = *(const float4*)(Ap);
    float4 pa1 = *(const float4*)(Ap + 4);
    float4 pb0 = *(const float4*)(Bp);
    float4 pb1 = *(const float4*)(Bp + 4);

    const int tr = lane >> 2;
    const int tc = lane & 3;

    for (int k0 = 0; k0 < K; k0 += 16) {
        *(float4*)&As[srow][skc]     = make_float4(to_tf32(pa0.x), to_tf32(pa0.y), to_tf32(pa0.z), to_tf32(pa0.w));
        *(float4*)&As[srow][skc + 4] = make_float4(to_tf32(pa1.x), to_tf32(pa1.y), to_tf32(pa1.z), to_tf32(pa1.w));
        *(float4*)&Bs[srow][skc]     = make_float4(to_tf32(pb0.x), to_tf32(pb0.y), to_tf32(pb0.z), to_tf32(pb0.w));
        *(float4*)&Bs[srow][skc + 4] = make_float4(to_tf32(pb1.x), to_tf32(pb1.y), to_tf32(pb1.z), to_tf32(pb1.w));
        __syncthreads();

        if (k0 + 16 < K) {
            pa0 = *(const float4*)(Ap + k0 + 16);
            pa1 = *(const float4*)(Ap + k0 + 20);
            pb0 = *(const float4*)(Bp + k0 + 16);
            pb1 = *(const float4*)(Bp + k0 + 20);
        }

        #pragma unroll
        for (int ks = 0; ks < 16; ks += 8) {
            uint32_t af[4][4], bf[4][2];
            #pragma unroll
            for (int mt = 0; mt < 4; mt++) {
                const int r0 = wm + mt * 16 + tr;
                af[mt][0] = __float_as_uint(As[r0    ][ks + tc    ]);
                af[mt][1] = __float_as_uint(As[r0 + 8][ks + tc    ]);
                af[mt][2] = __float_as_uint(As[r0    ][ks + tc + 4]);
                af[mt][3] = __float_as_uint(As[r0 + 8][ks + tc + 4]);
            }
            #pragma unroll
            for (int nt = 0; nt < 4; nt++) {
                const int c0 = wn + nt * 8 + tr;
                bf[nt][0] = __float_as_uint(Bs[c0][ks + tc    ]);
                bf[nt][1] = __float_as_uint(Bs[c0][ks + tc + 4]);
            }
            #pragma unroll
            for (int mt = 0; mt < 4; mt++)
                #pragma unroll
                for (int nt = 0; nt < 4; nt++)
                    mma_tf32(acc[mt][nt], af[mt], bf[nt]);
        }
        __syncthreads();
    }

    const int crow = (int)blockIdx.y * 128 + wm + tr;
    const int ccol = (int)blockIdx.x * 128 + wn + 2 * tc;
    #pragma unroll
    for (int mt = 0; mt < 4; mt++) {
        #pragma unroll
        for (int nt = 0; nt < 4; nt++) {
            float* Cp = C + (size_t)(crow + mt * 16) * N + ccol + nt * 8;
            *(float2*)Cp                   = make_float2(acc[mt][nt][0], acc[mt][nt][1]);
            *(float2*)(Cp + 8 * (size_t)N) = make_float2(acc[mt][nt][2], acc[mt][nt][3]);
        }
    }
}

// ------------- fused per-head RMSNorm + RoPE + Q/K/V scatter ---------------
__global__ __launch_bounds__(128) void norm_rope_kernel(
    const float* __restrict__ qkv,
    const float* __restrict__ cosT, const float* __restrict__ sinT,
    const float* __restrict__ q_ln, const float* __restrict__ k_ln)
{
    const int head = blockIdx.x;
    const int s    = blockIdx.y;
    const int b    = blockIdx.z;
    const int d    = threadIdx.x;

    const float x = qkv[((size_t)(b*S_ + s)) * QKV_N + head*D_ + d];

    __shared__ float red[4];
    __shared__ float sh[128];

    float v = x * x;
    #pragma unroll
    for (int o = 16; o > 0; o >>= 1) v += __shfl_xor_sync(0xffffffffu, v, o);
    if ((d & 31) == 0) red[d >> 5] = v;
    __syncthreads();

    if (head < H_ + HK_) {
        const float var = (red[0] + red[1] + red[2] + red[3]) * (1.0f / 128.0f);
        const float inv = rsqrtf(var + 1e-6f);
        const float* w  = (head < H_) ? q_ln : k_ln;
        const float y   = w[d] * x * inv;
        sh[d] = y;
        __syncthreads();

        float outv;
        if (d < R_) {
            const float c  = cosT[((size_t)(b*S_ + s)) * R_ + d];
            const float sn = sinT[((size_t)(b*S_ + s)) * R_ + d];
            const float rot = (d < R_/2) ? -sh[d + R_/2] : sh[d - R_/2];
            outv = y * c + rot * sn;
        } else {
            outv = y;
        }

        if (head < H_)
            g_q[(((size_t)(b*H_ + head)) * S_ + s) * D_ + d] = outv;
        else
            g_k[(((size_t)(b*HK_ + (head - H_))) * S_ + s) * D_ + d] = outv;
    } else {
        g_v[(((size_t)(b*HK_ + (head - H_ - HK_))) * S_ + s) * D_ + d] = x;
    }
}

// ----------------------- fp32 flash attention (GQA) ------------------------
// 128 threads/block, BM=64, 2 query rows per thread, BN=16 KV rows/iter.
// K/V smem swizzled: each 32-float quarter rotated by 2*quad float4s so the
// four quads' reads hit distinct bank groups (kills the 4-way conflict that
// made round-6's flash 4x slower than the traffic model).
__global__ __launch_bounds__(128) void flash_kernel()
{
    constexpr int BM = 64, BN = 16;
    __shared__ float Ks[BN][D_];
    __shared__ float Vs[BN][D_];

    const int tid  = threadIdx.x;         // 0..127
    const int bh   = blockIdx.y;
    const int b    = bh / H_;
    const int h    = bh % H_;
    const int hk   = h / (H_ / HK_);
    const int rp   = tid >> 2;            // 0..31: row pair index
    const int quad = tid & 3;
    const int cb   = quad * 32;
    const int q8   = quad * 8;            // phys float4 base of this quarter
    const int rot  = 2 * quad;            // swizzle rotation (float4 units)

    const size_t row0  = (size_t)blockIdx.x * BM + rp * 2;
    const float* qp0   = g_q + (((size_t)(b*H_ + h)) * S_ + row0    ) * D_ + cb;
    const float* qp1   = g_q + (((size_t)(b*H_ + h)) * S_ + row0 + 1) * D_ + cb;
    const float* kbase = g_k + ((size_t)(b*HK_ + hk)) * S_ * D_;
    const float* vbase = g_v + ((size_t)(b*HK_ + hk)) * S_ * D_;

    float4 qr0[8], qr1[8];
    #pragma unroll
    for (int i = 0; i < 8; i++) { qr0[i] = *(const float4*)(qp0 + i*4);
                                  qr1[i] = *(const float4*)(qp1 + i*4); }

    float o0[32], o1[32];
    #pragma unroll
    for (int i = 0; i < 32; i++) { o0[i] = 0.f; o1[i] = 0.f; }
    float m0 = -1e30f, l0 = 0.f, m1 = -1e30f, l1 = 0.f;
    const float sc = 0.08838834764831845f * 1.4426950408889634f; // scale*log2e

    for (int kb = 0; kb < S_; kb += BN) {
        // stage K/V with quarter-rotation swizzle: 512 float4 each, 4/thread
        const float4* ksrc = (const float4*)(kbase + (size_t)kb * D_);
        const float4* vsrc = (const float4*)(vbase + (size_t)kb * D_);
        #pragma unroll
        for (int t = 0; t < 4; t++) {
            const int idx = tid + t * 128;       // 0..511
            const int r   = idx >> 5;            // row 0..15
            const int u   = idx & 31;            // logical float4 in row
            const int pu  = (u & 24) | ((u + 2 * (u >> 3)) & 7);  // swizzled
            ((float4*)&Ks[r][0])[pu] = ksrc[idx];
            ((float4*)&Vs[r][0])[pu] = vsrc[idx];
        }
        __syncthreads();

        float s0[BN], s1[BN];
        #pragma unroll
        for (int j = 0; j < BN; j++) {
            float a0 = 0.f, a1 = 0.f;
            const float4* kp = (const float4*)&Ks[j][0];
            #pragma unroll
            for (int i = 0; i < 8; i++) {
                const float4 kk = kp[q8 + ((i + rot) & 7)];  // logical chunk i
                a0 += qr0[i].x*kk.x + qr0[i].y*kk.y + qr0[i].z*kk.z + qr0[i].w*kk.w;
                a1 += qr1[i].x*kk.x + qr1[i].y*kk.y + qr1[i].z*kk.z + qr1[i].w*kk.w;
            }
            a0 += __shfl_xor_sync(0xffffffffu, a0, 1);
            a0 += __shfl_xor_sync(0xffffffffu, a0, 2);
            a1 += __shfl_xor_sync(0xffffffffu, a1, 1);
            a1 += __shfl_xor_sync(0xffffffffu, a1, 2);
            s0[j] = a0 * sc;
            s1[j] = a1 * sc;
        }

        float t0 = s0[0], t1 = s1[0];
        #pragma unroll
        for (int j = 1; j < BN; j++) { t0 = fmaxf(t0, s0[j]); t1 = fmaxf(t1, s1[j]); }
        const float m0n = fmaxf(m0, t0), m1n = fmaxf(m1, t1);
        const float al0 = exp2f(m0 - m0n), al1 = exp2f(m1 - m1n);
        l0 *= al0; l1 *= al1;
        #pragma unroll
        for (int i = 0; i < 32; i++) { o0[i] *= al0; o1[i] *= al1; }

        #pragma unroll
        for (int j = 0; j < BN; j++) {
            const float p0 = exp2f(s0[j] - m0n);
            const float p1 = exp2f(s1[j] - m1n);
            l0 += p0; l1 += p1;
            const float4* vp = (const float4*)&Vs[j][0];
            #pragma unroll
            for (int i = 0; i < 8; i++) {
                const float4 vv = vp[q8 + ((i + rot) & 7)];
                o0[4*i+0] += p0 * vv.x; o0[4*i+1] += p0 * vv.y;
                o0[4*i+2] += p0 * vv.z; o0[4*i+3] += p0 * vv.w;
                o1[4*i+0] += p1 * vv.x; o1[4*i+1] += p1 * vv.y;
                o1[4*i+2] += p1 * vv.z; o1[4*i+3] += p1 * vv.w;
            }
        }
        m0 = m0n; m1 = m1n;
        __syncthreads();
    }

    const float iv0 = 1.0f / l0, iv1 = 1.0f / l1;
    float* op0 = g_attn + ((size_t)b * S_ + row0    ) * HID_ + h*D_ + cb;
    float* op1 = g_attn + ((size_t)b * S_ + row0 + 1) * HID_ + h*D_ + cb;
    #pragma unroll
    for (int i = 0; i < 8; i++) {
        ((float4*)op0)[i] = make_float4(o0[4*i]*iv0, o0[4*i+1]*iv0, o0[4*i+2]*iv0, o0[4*i+3]*iv0);
        ((float4*)op1)[i] = make_float4(o1[4*i]*iv1, o1[4*i+1]*iv1, o1[4*i+2]*iv1, o1[4*i+3]*iv1);
    }
}

// ------------------------------- launch ------------------------------------
extern "C" void kernel_launch(void* const* d_in, const int* in_sizes, int n_in,
                              void* d_out, int out_size)
{
    const float* hidden  = (const float*)d_in[0];
    const float* cosT    = (const float*)d_in[1];
    const float* sinT    = (const float*)d_in[2];
    const float* w_qkv   = (const float*)d_in[3];
    const float* q_ln    = (const float*)d_in[4];
    const float* k_ln    = (const float*)d_in[5];
    const float* w_dense = (const float*)d_in[6];
    float* out = (float*)d_out;

    float *qkv_ptr, *attn_ptr;
    cudaGetSymbolAddress((void**)&qkv_ptr,  g_qkv);
    cudaGetSymbolAddress((void**)&attn_ptr, g_attn);

    // 1) QKV projection
    {
        dim3 grid(QKV_N/128, M_/128);
        gemm_tf32_nt<<<grid, 256>>>(hidden, w_qkv, qkv_ptr, M_, QKV_N, HID_);
    }
    // 2) RMSNorm + RoPE + scatter
    {
        dim3 grid(H_ + 2*HK_, S_, B_);
        norm_rope_kernel<<<grid, 128>>>(qkv_ptr, cosT, sinT, q_ln, k_ln);
    }
    // 3) Flash attention
    {
        dim3 grid(S_/64, B_*H_);
        flash_kernel<<<grid, 128>>>();
    }
    // 4) Output projection
    {
        dim3 grid(HID_/128, M_/128);
        gemm_tf32_nt<<<grid, 256>>>(attn_ptr, w_dense, out, M_, HID_, HID_);
    }
}

// round 14
// speedup vs baseline: 9.8550x; 2.0806x over previous
#include <cuda_runtime.h>
#include <math.h>
#include <stdint.h>

#define B_    2
#define S_    2048
#define HID_  2048
#define H_    16
#define HK_   4
#define D_    128
#define R_    64
#define QKV_N 3072
#define M_    (B_*S_)   // 4096

// ---------------- scratch (device globals: allocation-free) ----------------
__device__ float g_qkv[(size_t)M_ * QKV_N];
__device__ float g_q[(size_t)B_*H_*S_*D_];
__device__ float g_k[(size_t)B_*HK_*S_*D_];
__device__ float g_v[(size_t)B_*HK_*S_*D_];
__device__ float g_attn[(size_t)M_ * HID_];

// ---------------------------------------------------------------------------
// tf32 helpers
// ---------------------------------------------------------------------------
__device__ __forceinline__ float to_tf32(float x) {
    uint32_t u;
    asm("cvt.rna.tf32.f32 %0, %1;" : "=r"(u) : "f"(x));
    return __uint_as_float(u);
}

__device__ __forceinline__ void mma_tf32(float* d, const uint32_t* a, const uint32_t* b) {
    asm volatile(
        "mma.sync.aligned.m16n8k8.row.col.f32.tf32.tf32.f32 "
        "{%0,%1,%2,%3}, {%4,%5,%6,%7}, {%8,%9}, {%0,%1,%2,%3};"
        : "+f"(d[0]), "+f"(d[1]), "+f"(d[2]), "+f"(d[3])
        : "r"(a[0]), "r"(a[1]), "r"(a[2]), "r"(a[3]), "r"(b[0]), "r"(b[1]));
}

// ---------------------------------------------------------------------------
// tf32 tensor-core GEMM: C[M,N] = A[M,K] * B[N,K]^T  (both K-contiguous)
// (unchanged from round-11 measured-good version)
// ---------------------------------------------------------------------------
#define GP 20

__global__ __launch_bounds__(256) void gemm_tf32_nt(
    const float* __restrict__ A, const float* __restrict__ Bm,
    float* __restrict__ C, int M, int N, int K)
{
    __shared__ float As[128][GP];
    __shared__ float Bs[128][GP];

    const int tid  = threadIdx.x;
    const int lane = tid & 31;
    const int warp = tid >> 5;
    const int wm   = (warp >> 2) * 64;
    const int wn   = (warp & 3) * 32;

    const int srow = tid >> 1;
    const int skc  = (tid & 1) * 8;

    const float* Ap = A  + ((size_t)blockIdx.y * 128 + srow) * K + skc;
    const float* Bp = Bm + ((size_t)blockIdx.x * 128 + srow) * K + skc;

    float acc[4][4][4];
    #pragma unroll
    for (int i = 0; i < 4; i++)
        #pragma unroll
        for (int j = 0; j < 4; j++)
            #pragma unroll
            for (int r = 0; r < 4; r++) acc[i][j][r] = 0.f;

    float4 pa0 = *(const float4*)(Ap);
    float4 pa1 = *(const float4*)(Ap + 4);
    float4 pb0 = *(const float4*)(Bp);
    float4 pb1 = *(const float4*)(Bp + 4);

    const int tr = lane >> 2;
    const int tc = lane & 3;

    for (int k0 = 0; k0 < K; k0 += 16) {
        *(float4*)&As[srow][skc]     = make_float4(to_tf32(pa0.x), to_tf32(pa0.y), to_tf32(pa0.z), to_tf32(pa0.w));
        *(float4*)&As[srow][skc + 4] = make_float4(to_tf32(pa1.x), to_tf32(pa1.y), to_tf32(pa1.z), to_tf32(pa1.w));
        *(float4*)&Bs[srow][skc]     = make_float4(to_tf32(pb0.x), to_tf32(pb0.y), to_tf32(pb0.z), to_tf32(pb0.w));
        *(float4*)&Bs[srow][skc + 4] = make_float4(to_tf32(pb1.x), to_tf32(pb1.y), to_tf32(pb1.z), to_tf32(pb1.w));
        __syncthreads();

        if (k0 + 16 < K) {
            pa0 = *(const float4*)(Ap + k0 + 16);
            pa1 = *(const float4*)(Ap + k0 + 20);
            pb0 = *(const float4*)(Bp + k0 + 16);
            pb1 = *(const float4*)(Bp + k0 + 20);
        }

        #pragma unroll
        for (int ks = 0; ks < 16; ks += 8) {
            uint32_t af[4][4], bf[4][2];
            #pragma unroll
            for (int mt = 0; mt < 4; mt++) {
                const int r0 = wm + mt * 16 + tr;
                af[mt][0] = __float_as_uint(As[r0    ][ks + tc    ]);
                af[mt][1] = __float_as_uint(As[r0 + 8][ks + tc    ]);
                af[mt][2] = __float_as_uint(As[r0    ][ks + tc + 4]);
                af[mt][3] = __float_as_uint(As[r0 + 8][ks + tc + 4]);
            }
            #pragma unroll
            for (int nt = 0; nt < 4; nt++) {
                const int c0 = wn + nt * 8 + tr;
                bf[nt][0] = __float_as_uint(Bs[c0][ks + tc    ]);
                bf[nt][1] = __float_as_uint(Bs[c0][ks + tc + 4]);
            }
            #pragma unroll
            for (int mt = 0; mt < 4; mt++)
                #pragma unroll
                for (int nt = 0; nt < 4; nt++)
                    mma_tf32(acc[mt][nt], af[mt], bf[nt]);
        }
        __syncthreads();
    }

    const int crow = (int)blockIdx.y * 128 + wm + tr;
    const int ccol = (int)blockIdx.x * 128 + wn + 2 * tc;
    #pragma unroll
    for (int mt = 0; mt < 4; mt++) {
        #pragma unroll
        for (int nt = 0; nt < 4; nt++) {
            float* Cp = C + (size_t)(crow + mt * 16) * N + ccol + nt * 8;
            *(float2*)Cp                   = make_float2(acc[mt][nt][0], acc[mt][nt][1]);
            *(float2*)(Cp + 8 * (size_t)N) = make_float2(acc[mt][nt][2], acc[mt][nt][3]);
        }
    }
}

// ------------- fused per-head RMSNorm + RoPE + Q/K/V scatter ---------------
__global__ __launch_bounds__(128) void norm_rope_kernel(
    const float* __restrict__ qkv,
    const float* __restrict__ cosT, const float* __restrict__ sinT,
    const float* __restrict__ q_ln, const float* __restrict__ k_ln)
{
    const int head = blockIdx.x;
    const int s    = blockIdx.y;
    const int b    = blockIdx.z;
    const int d    = threadIdx.x;

    const float x = qkv[((size_t)(b*S_ + s)) * QKV_N + head*D_ + d];

    __shared__ float red[4];
    __shared__ float sh[128];

    float v = x * x;
    #pragma unroll
    for (int o = 16; o > 0; o >>= 1) v += __shfl_xor_sync(0xffffffffu, v, o);
    if ((d & 31) == 0) red[d >> 5] = v;
    __syncthreads();

    if (head < H_ + HK_) {
        const float var = (red[0] + red[1] + red[2] + red[3]) * (1.0f / 128.0f);
        const float inv = rsqrtf(var + 1e-6f);
        const float* w  = (head < H_) ? q_ln : k_ln;
        const float y   = w[d] * x * inv;
        sh[d] = y;
        __syncthreads();

        float outv;
        if (d < R_) {
            const float c  = cosT[((size_t)(b*S_ + s)) * R_ + d];
            const float sn = sinT[((size_t)(b*S_ + s)) * R_ + d];
            const float rot = (d < R_/2) ? -sh[d + R_/2] : sh[d - R_/2];
            outv = y * c + rot * sn;
        } else {
            outv = y;
        }

        if (head < H_)
            g_q[(((size_t)(b*H_ + head)) * S_ + s) * D_ + d] = outv;
        else
            g_k[(((size_t)(b*HK_ + (head - H_))) * S_ + s) * D_ + d] = outv;
    } else {
        g_v[(((size_t)(b*HK_ + (head - H_ - HK_))) * S_ + s) * D_ + d] = x;
    }
}

// ---------------------------------------------------------------------------
// tf32 tensor-core flash attention (GQA).
// 4 warps, BM=64 (16 Q-rows/warp), BN=32 KV/iter.
// QKt: A=Q frags (regs, loop-invariant), B=K smem pitch 132 (4tr+tc banks).
// PV : A=P via warp-private smem slab pitch 36, B=V smem pitch 136 (8tc+tr).
// Fragment layouts identical to the HW-validated gemm_tf32_nt mapping.
// ---------------------------------------------------------------------------
#define KP 132   // K smem pitch (floats): frag reads 4tr+tc -> conflict-free
#define VP 136   // V smem pitch (floats): frag reads 8tc+tr -> conflict-free
#define PP 36    // P smem pitch (floats): frag reads 4tr+tc -> conflict-free

__global__ __launch_bounds__(128) void flash_mma_kernel()
{
    __shared__ float Ks[32][KP];
    __shared__ float Vs[32][VP];
    __shared__ float Ps[64][PP];

    const int tid  = threadIdx.x;
    const int lane = tid & 31;
    const int warp = tid >> 5;      // 0..3
    const int tr   = lane >> 2;     // 0..7
    const int tc   = lane & 3;      // 0..3
    const int lr   = warp * 16;     // warp's local Q-row base (0..48)

    const int bh = blockIdx.y;
    const int b  = bh / H_;
    const int h  = bh % H_;
    const int hk = h / (H_ / HK_);

    const float* qbase = g_q + ((size_t)(b*H_ + h)) * S_ * D_;
    const float* kbase = g_k + ((size_t)(b*HK_ + hk)) * S_ * D_;
    const float* vbase = g_v + ((size_t)(b*HK_ + hk)) * S_ * D_;
    const size_t qrow0 = (size_t)blockIdx.x * 64;

    const float sc = 0.08838834764831845f * 1.4426950408889634f; // 1/sqrt(D)*log2e

    // ---- load Q fragments (pre-scaled, tf32), staged through Ks ----------
    uint32_t qf[16][4];
    #pragma unroll
    for (int half = 0; half < 2; half++) {
        #pragma unroll
        for (int t = 0; t < 8; t++) {
            const int idx = tid + t * 128;        // 0..1023 float4s
            const int r   = idx >> 5;             // 0..31
            const int c4  = idx & 31;
            float4 qv = *(const float4*)(qbase + (qrow0 + half*32 + r) * D_ + c4*4);
            *(float4*)&Ks[r][c4*4] = make_float4(to_tf32(qv.x*sc), to_tf32(qv.y*sc),
                                                 to_tf32(qv.z*sc), to_tf32(qv.w*sc));
        }
        __syncthreads();
        if ((warp >> 1) == half) {
            const int r0 = (warp & 1) * 16;
            #pragma unroll
            for (int ks = 0; ks < 16; ks++) {
                qf[ks][0] = __float_as_uint(Ks[r0 + tr    ][ks*8 + tc    ]);
                qf[ks][1] = __float_as_uint(Ks[r0 + tr + 8][ks*8 + tc    ]);
                qf[ks][2] = __float_as_uint(Ks[r0 + tr    ][ks*8 + tc + 4]);
                qf[ks][3] = __float_as_uint(Ks[r0 + tr + 8][ks*8 + tc + 4]);
            }
        }
        __syncthreads();
    }

    float o[16][4];
    #pragma unroll
    for (int nt = 0; nt < 16; nt++)
        #pragma unroll
        for (int r = 0; r < 4; r++) o[nt][r] = 0.f;
    float m0 = -1e30f, m1 = -1e30f, l0 = 0.f, l1 = 0.f;

    for (int kb = 0; kb < S_; kb += 32) {
        // ---- stage K (pitch 132) and V (pitch 136), tf32-rounded ---------
        const float4* ksrc = (const float4*)(kbase + (size_t)kb * D_);
        const float4* vsrc = (const float4*)(vbase + (size_t)kb * D_);
        #pragma unroll
        for (int t = 0; t < 8; t++) {
            const int idx = tid + t * 128;
            const int r   = idx >> 5;
            const int c4  = idx & 31;
            float4 kv = ksrc[idx];
            float4 vv = vsrc[idx];
            *(float4*)&Ks[r][c4*4] = make_float4(to_tf32(kv.x), to_tf32(kv.y),
                                                 to_tf32(kv.z), to_tf32(kv.w));
            *(float4*)&Vs[r][c4*4] = make_float4(to_tf32(vv.x), to_tf32(vv.y),
                                                 to_tf32(vv.z), to_tf32(vv.w));
        }
        __syncthreads();

        // ---- S = Q Kt : 4 n-tiles x 16 k-steps ---------------------------
        float s[4][4];
        #pragma unroll
        for (int nt = 0; nt < 4; nt++) {
            s[nt][0] = s[nt][1] = s[nt][2] = s[nt][3] = 0.f;
            #pragma unroll
            for (int ks = 0; ks < 16; ks++) {
                uint32_t bfr[2];
                bfr[0] = __float_as_uint(Ks[nt*8 + tr][ks*8 + tc    ]);
                bfr[1] = __float_as_uint(Ks[nt*8 + tr][ks*8 + tc + 4]);
                mma_tf32(s[nt], qf[ks], bfr);
            }
        }

        // ---- online softmax on fragments ---------------------------------
        float mx0 = s[0][0], mx1 = s[0][2];
        #pragma unroll
        for (int nt = 0; nt < 4; nt++) {
            mx0 = fmaxf(mx0, fmaxf(s[nt][0], s[nt][1]));
            mx1 = fmaxf(mx1, fmaxf(s[nt][2], s[nt][3]));
        }
        mx0 = fmaxf(mx0, __shfl_xor_sync(0xffffffffu, mx0, 1));
        mx0 = fmaxf(mx0, __shfl_xor_sync(0xffffffffu, mx0, 2));
        mx1 = fmaxf(mx1, __shfl_xor_sync(0xffffffffu, mx1, 1));
        mx1 = fmaxf(mx1, __shfl_xor_sync(0xffffffffu, mx1, 2));

        const float m0n = fmaxf(m0, mx0), m1n = fmaxf(m1, mx1);
        const float al0 = exp2f(m0 - m0n), al1 = exp2f(m1 - m1n);
        m0 = m0n; m1 = m1n;

        float ls0 = 0.f, ls1 = 0.f;
        #pragma unroll
        for (int nt = 0; nt < 4; nt++) {
            const float p0 = exp2f(s[nt][0] - m0), p1 = exp2f(s[nt][1] - m0);
            const float p2 = exp2f(s[nt][2] - m1), p3 = exp2f(s[nt][3] - m1);
            ls0 += p0 + p1; ls1 += p2 + p3;
            *(float2*)&Ps[lr + tr    ][nt*8 + 2*tc] = make_float2(to_tf32(p0), to_tf32(p1));
            *(float2*)&Ps[lr + tr + 8][nt*8 + 2*tc] = make_float2(to_tf32(p2), to_tf32(p3));
        }
        ls0 += __shfl_xor_sync(0xffffffffu, ls0, 1);
        ls0 += __shfl_xor_sync(0xffffffffu, ls0, 2);
        ls1 += __shfl_xor_sync(0xffffffffu, ls1, 1);
        ls1 += __shfl_xor_sync(0xffffffffu, ls1, 2);
        l0 = l0 * al0 + ls0;
        l1 = l1 * al1 + ls1;

        #pragma unroll
        for (int nt = 0; nt < 16; nt++) {
            o[nt][0] *= al0; o[nt][1] *= al0;
            o[nt][2] *= al1; o[nt][3] *= al1;
        }
        __syncwarp();

        // ---- O += P V : A frags from warp-private P slab -----------------
        uint32_t pa[4][4];
        #pragma unroll
        for (int ks = 0; ks < 4; ks++) {
            pa[ks][0] = __float_as_uint(Ps[lr + tr    ][ks*8 + tc    ]);
            pa[ks][1] = __float_as_uint(Ps[lr + tr + 8][ks*8 + tc    ]);
            pa[ks][2] = __float_as_uint(Ps[lr + tr    ][ks*8 + tc + 4]);
            pa[ks][3] = __float_as_uint(Ps[lr + tr + 8][ks*8 + tc + 4]);
        }
        #pragma unroll
        for (int nt = 0; nt < 16; nt++) {
            #pragma unroll
            for (int ks = 0; ks < 4; ks++) {
                uint32_t bfr[2];
                bfr[0] = __float_as_uint(Vs[ks*8 + tc    ][nt*8 + tr]);
                bfr[1] = __float_as_uint(Vs[ks*8 + tc + 4][nt*8 + tr]);
                mma_tf32(o[nt], pa[ks], bfr);
            }
        }
        __syncthreads();
    }

    // ---- epilogue ---------------------------------------------------------
    const float iv0 = 1.0f / l0, iv1 = 1.0f / l1;
    const size_t row0 = (size_t)b * S_ + qrow0 + lr + tr;
    float* op0 = g_attn + row0 * HID_ + h*D_ + 2*tc;
    float* op1 = g_attn + (row0 + 8) * HID_ + h*D_ + 2*tc;
    #pragma unroll
    for (int nt = 0; nt < 16; nt++) {
        *(float2*)(op0 + nt*8) = make_float2(o[nt][0]*iv0, o[nt][1]*iv0);
        *(float2*)(op1 + nt*8) = make_float2(o[nt][2]*iv1, o[nt][3]*iv1);
    }
}

// ------------------------------- launch ------------------------------------
extern "C" void kernel_launch(void* const* d_in, const int* in_sizes, int n_in,
                              void* d_out, int out_size)
{
    const float* hidden  = (const float*)d_in[0];
    const float* cosT    = (const float*)d_in[1];
    const float* sinT    = (const float*)d_in[2];
    const float* w_qkv   = (const float*)d_in[3];
    const float* q_ln    = (const float*)d_in[4];
    const float* k_ln    = (const float*)d_in[5];
    const float* w_dense = (const float*)d_in[6];
    float* out = (float*)d_out;

    float *qkv_ptr, *attn_ptr;
    cudaGetSymbolAddress((void**)&qkv_ptr,  g_qkv);
    cudaGetSymbolAddress((void**)&attn_ptr, g_attn);

    // 1) QKV projection
    {
        dim3 grid(QKV_N/128, M_/128);
        gemm_tf32_nt<<<grid, 256>>>(hidden, w_qkv, qkv_ptr, M_, QKV_N, HID_);
    }
    // 2) RMSNorm + RoPE + scatter
    {
        dim3 grid(H_ + 2*HK_, S_, B_);
        norm_rope_kernel<<<grid, 128>>>(qkv_ptr, cosT, sinT, q_ln, k_ln);
    }
    // 3) Flash attention (tf32 mma)
    {
        dim3 grid(S_/64, B_*H_);
        flash_mma_kernel<<<grid, 128>>>();
    }
    // 4) Output projection
    {
        dim3 grid(HID_/128, M_/128);
        gemm_tf32_nt<<<grid, 256>>>(attn_ptr, w_dense, out, M_, HID_, HID_);
    }
}

// round 17
// speedup vs baseline: 11.9358x; 1.2111x over previous
#include <cuda_runtime.h>
#include <math.h>
#include <stdint.h>

#define B_    2
#define S_    2048
#define HID_  2048
#define H_    16
#define HK_   4
#define D_    128
#define R_    64
#define QKV_N 3072
#define M_    (B_*S_)   // 4096

// ---------------- scratch (device globals: allocation-free) ----------------
__device__ float g_qkv[(size_t)M_ * QKV_N];
__device__ float g_q[(size_t)B_*H_*S_*D_];
__device__ float g_k[(size_t)B_*HK_*S_*D_];
__device__ float g_v[(size_t)B_*HK_*S_*D_];
__device__ float g_attn[(size_t)M_ * HID_];

// ---------------------------------------------------------------------------
// tf32 helpers
// ---------------------------------------------------------------------------
__device__ __forceinline__ float to_tf32(float x) {
    uint32_t u;
    asm("cvt.rna.tf32.f32 %0, %1;" : "=r"(u) : "f"(x));
    return __uint_as_float(u);
}

__device__ __forceinline__ void mma_tf32(float* d, const uint32_t* a, const uint32_t* b) {
    asm volatile(
        "mma.sync.aligned.m16n8k8.row.col.f32.tf32.tf32.f32 "
        "{%0,%1,%2,%3}, {%4,%5,%6,%7}, {%8,%9}, {%0,%1,%2,%3};"
        : "+f"(d[0]), "+f"(d[1]), "+f"(d[2]), "+f"(d[3])
        : "r"(a[0]), "r"(a[1]), "r"(a[2]), "r"(a[3]), "r"(b[0]), "r"(b[1]));
}

// ---------------------------------------------------------------------------
// tf32 tensor-core GEMM: C[M,N] = A[M,K] * B[N,K]^T  (both K-contiguous)
// 128x128x16 block tile, 4 warps, each warp 64x64 via 4x8 m16n8k8 tiles.
// (round-15: widened warp tile for 1.5x better mma/LDS ratio; accumulation
//  order per output element unchanged -> bit-identical to round-14 GEMM)
// ---------------------------------------------------------------------------
#define GP 20

__global__ __launch_bounds__(128) void gemm_tf32_nt(
    const float* __restrict__ A, const float* __restrict__ Bm,
    float* __restrict__ C, int M, int N, int K)
{
    __shared__ float As[128][GP];
    __shared__ float Bs[128][GP];

    const int tid  = threadIdx.x;
    const int lane = tid & 31;
    const int warp = tid >> 5;           // 0..3
    const int wm   = (warp & 1) * 64;    // warp m-offset (0/64)
    const int wn   = (warp >> 1) * 64;   // warp n-offset (0/64)

    // staging: thread stages 4 float4 for A and 4 for B per 16-K slab
    const int srow = tid >> 2;           // 0..31 (+32 per t)
    const int scol = (tid & 3) * 4;      // float col 0/4/8/12

    const float* Ap = A  + ((size_t)blockIdx.y * 128 + srow) * K + scol;
    const float* Bp = Bm + ((size_t)blockIdx.x * 128 + srow) * K + scol;

    float acc[4][8][4];
    #pragma unroll
    for (int i = 0; i < 4; i++)
        #pragma unroll
        for (int j = 0; j < 8; j++)
            #pragma unroll
            for (int r = 0; r < 4; r++) acc[i][j][r] = 0.f;

    float4 pa[4], pb[4];
    #pragma unroll
    for (int t = 0; t < 4; t++) {
        pa[t] = *(const float4*)(Ap + (size_t)t * 32 * K);
        pb[t] = *(const float4*)(Bp + (size_t)t * 32 * K);
    }

    const int tr = lane >> 2;
    const int tc = lane & 3;

    for (int k0 = 0; k0 < K; k0 += 16) {
        #pragma unroll
        for (int t = 0; t < 4; t++) {
            *(float4*)&As[srow + t*32][scol] =
                make_float4(to_tf32(pa[t].x), to_tf32(pa[t].y), to_tf32(pa[t].z), to_tf32(pa[t].w));
            *(float4*)&Bs[srow + t*32][scol] =
                make_float4(to_tf32(pb[t].x), to_tf32(pb[t].y), to_tf32(pb[t].z), to_tf32(pb[t].w));
        }
        __syncthreads();

        if (k0 + 16 < K) {
            #pragma unroll
            for (int t = 0; t < 4; t++) {
                pa[t] = *(const float4*)(Ap + (size_t)t * 32 * K + k0 + 16);
                pb[t] = *(const float4*)(Bp + (size_t)t * 32 * K + k0 + 16);
            }
        }

        #pragma unroll
        for (int ks = 0; ks < 16; ks += 8) {
            uint32_t af[4][4], bf[8][2];
            #pragma unroll
            for (int mt = 0; mt < 4; mt++) {
                const int r0 = wm + mt * 16 + tr;
                af[mt][0] = __float_as_uint(As[r0    ][ks + tc    ]);
                af[mt][1] = __float_as_uint(As[r0 + 8][ks + tc    ]);
                af[mt][2] = __float_as_uint(As[r0    ][ks + tc + 4]);
                af[mt][3] = __float_as_uint(As[r0 + 8][ks + tc + 4]);
            }
            #pragma unroll
            for (int nt = 0; nt < 8; nt++) {
                const int c0 = wn + nt * 8 + tr;
                bf[nt][0] = __float_as_uint(Bs[c0][ks + tc    ]);
                bf[nt][1] = __float_as_uint(Bs[c0][ks + tc + 4]);
            }
            #pragma unroll
            for (int mt = 0; mt < 4; mt++)
                #pragma unroll
                for (int nt = 0; nt < 8; nt++)
                    mma_tf32(acc[mt][nt], af[mt], bf[nt]);
        }
        __syncthreads();
    }

    const int crow = (int)blockIdx.y * 128 + wm + tr;
    const int ccol = (int)blockIdx.x * 128 + wn + 2 * tc;
    #pragma unroll
    for (int mt = 0; mt < 4; mt++) {
        #pragma unroll
        for (int nt = 0; nt < 8; nt++) {
            float* Cp = C + (size_t)(crow + mt * 16) * N + ccol + nt * 8;
            *(float2*)Cp                   = make_float2(acc[mt][nt][0], acc[mt][nt][1]);
            *(float2*)(Cp + 8 * (size_t)N) = make_float2(acc[mt][nt][2], acc[mt][nt][3]);
        }
    }
}

// ------------- fused per-head RMSNorm + RoPE + Q/K/V scatter ---------------
__global__ __launch_bounds__(128) void norm_rope_kernel(
    const float* __restrict__ qkv,
    const float* __restrict__ cosT, const float* __restrict__ sinT,
    const float* __restrict__ q_ln, const float* __restrict__ k_ln)
{
    const int head = blockIdx.x;
    const int s    = blockIdx.y;
    const int b    = blockIdx.z;
    const int d    = threadIdx.x;

    const float x = qkv[((size_t)(b*S_ + s)) * QKV_N + head*D_ + d];

    __shared__ float red[4];
    __shared__ float sh[128];

    float v = x * x;
    #pragma unroll
    for (int o = 16; o > 0; o >>= 1) v += __shfl_xor_sync(0xffffffffu, v, o);
    if ((d & 31) == 0) red[d >> 5] = v;
    __syncthreads();

    if (head < H_ + HK_) {
        const float var = (red[0] + red[1] + red[2] + red[3]) * (1.0f / 128.0f);
        const float inv = rsqrtf(var + 1e-6f);
        const float* w  = (head < H_) ? q_ln : k_ln;
        const float y   = w[d] * x * inv;
        sh[d] = y;
        __syncthreads();

        float outv;
        if (d < R_) {
            const float c  = cosT[((size_t)(b*S_ + s)) * R_ + d];
            const float sn = sinT[((size_t)(b*S_ + s)) * R_ + d];
            const float rot = (d < R_/2) ? -sh[d + R_/2] : sh[d - R_/2];
            outv = y * c + rot * sn;
        } else {
            outv = y;
        }

        if (head < H_)
            g_q[(((size_t)(b*H_ + head)) * S_ + s) * D_ + d] = outv;
        else
            g_k[(((size_t)(b*HK_ + (head - H_))) * S_ + s) * D_ + d] = outv;
    } else {
        g_v[(((size_t)(b*HK_ + (head - H_ - HK_))) * S_ + s) * D_ + d] = x;
    }
}

// ---------------------------------------------------------------------------
// tf32 tensor-core flash attention (GQA) — round-14 measured-good version.
// ---------------------------------------------------------------------------
#define KP 132
#define VP 136
#define PP 36

__global__ __launch_bounds__(128) void flash_mma_kernel()
{
    __shared__ float Ks[32][KP];
    __shared__ float Vs[32][VP];
    __shared__ float Ps[64][PP];

    const int tid  = threadIdx.x;
    const int lane = tid & 31;
    const int warp = tid >> 5;
    const int tr   = lane >> 2;
    const int tc   = lane & 3;
    const int lr   = warp * 16;

    const int bh = blockIdx.y;
    const int b  = bh / H_;
    const int h  = bh % H_;
    const int hk = h / (H_ / HK_);

    const float* qbase = g_q + ((size_t)(b*H_ + h)) * S_ * D_;
    const float* kbase = g_k + ((size_t)(b*HK_ + hk)) * S_ * D_;
    const float* vbase = g_v + ((size_t)(b*HK_ + hk)) * S_ * D_;
    const size_t qrow0 = (size_t)blockIdx.x * 64;

    const float sc = 0.08838834764831845f * 1.4426950408889634f;

    uint32_t qf[16][4];
    #pragma unroll
    for (int half = 0; half < 2; half++) {
        #pragma unroll
        for (int t = 0; t < 8; t++) {
            const int idx = tid + t * 128;
            const int r   = idx >> 5;
            const int c4  = idx & 31;
            float4 qv = *(const float4*)(qbase + (qrow0 + half*32 + r) * D_ + c4*4);
            *(float4*)&Ks[r][c4*4] = make_float4(to_tf32(qv.x*sc), to_tf32(qv.y*sc),
                                                 to_tf32(qv.z*sc), to_tf32(qv.w*sc));
        }
        __syncthreads();
        if ((warp >> 1) == half) {
            const int r0 = (warp & 1) * 16;
            #pragma unroll
            for (int ks = 0; ks < 16; ks++) {
                qf[ks][0] = __float_as_uint(Ks[r0 + tr    ][ks*8 + tc    ]);
                qf[ks][1] = __float_as_uint(Ks[r0 + tr + 8][ks*8 + tc    ]);
                qf[ks][2] = __float_as_uint(Ks[r0 + tr    ][ks*8 + tc + 4]);
                qf[ks][3] = __float_as_uint(Ks[r0 + tr + 8][ks*8 + tc + 4]);
            }
        }
        __syncthreads();
    }

    float o[16][4];
    #pragma unroll
    for (int nt = 0; nt < 16; nt++)
        #pragma unroll
        for (int r = 0; r < 4; r++) o[nt][r] = 0.f;
    float m0 = -1e30f, m1 = -1e30f, l0 = 0.f, l1 = 0.f;

    for (int kb = 0; kb < S_; kb += 32) {
        const float4* ksrc = (const float4*)(kbase + (size_t)kb * D_);
        const float4* vsrc = (const float4*)(vbase + (size_t)kb * D_);
        #pragma unroll
        for (int t = 0; t < 8; t++) {
            const int idx = tid + t * 128;
            const int r   = idx >> 5;
            const int c4  = idx & 31;
            float4 kv = ksrc[idx];
            float4 vv = vsrc[idx];
            *(float4*)&Ks[r][c4*4] = make_float4(to_tf32(kv.x), to_tf32(kv.y),
                                                 to_tf32(kv.z), to_tf32(kv.w));
            *(float4*)&Vs[r][c4*4] = make_float4(to_tf32(vv.x), to_tf32(vv.y),
                                                 to_tf32(vv.z), to_tf32(vv.w));
        }
        __syncthreads();

        float s[4][4];
        #pragma unroll
        for (int nt = 0; nt < 4; nt++) {
            s[nt][0] = s[nt][1] = s[nt][2] = s[nt][3] = 0.f;
            #pragma unroll
            for (int ks = 0; ks < 16; ks++) {
                uint32_t bfr[2];
                bfr[0] = __float_as_uint(Ks[nt*8 + tr][ks*8 + tc    ]);
                bfr[1] = __float_as_uint(Ks[nt*8 + tr][ks*8 + tc + 4]);
                mma_tf32(s[nt], qf[ks], bfr);
            }
        }

        float mx0 = s[0][0], mx1 = s[0][2];
        #pragma unroll
        for (int nt = 0; nt < 4; nt++) {
            mx0 = fmaxf(mx0, fmaxf(s[nt][0], s[nt][1]));
            mx1 = fmaxf(mx1, fmaxf(s[nt][2], s[nt][3]));
        }
        mx0 = fmaxf(mx0, __shfl_xor_sync(0xffffffffu, mx0, 1));
        mx0 = fmaxf(mx0, __shfl_xor_sync(0xffffffffu, mx0, 2));
        mx1 = fmaxf(mx1, __shfl_xor_sync(0xffffffffu, mx1, 1));
        mx1 = fmaxf(mx1, __shfl_xor_sync(0xffffffffu, mx1, 2));

        const float m0n = fmaxf(m0, mx0), m1n = fmaxf(m1, mx1);
        const float al0 = exp2f(m0 - m0n), al1 = exp2f(m1 - m1n);
        m0 = m0n; m1 = m1n;

        float ls0 = 0.f, ls1 = 0.f;
        #pragma unroll
        for (int nt = 0; nt < 4; nt++) {
            const float p0 = exp2f(s[nt][0] - m0), p1 = exp2f(s[nt][1] - m0);
            const float p2 = exp2f(s[nt][2] - m1), p3 = exp2f(s[nt][3] - m1);
            ls0 += p0 + p1; ls1 += p2 + p3;
            *(float2*)&Ps[lr + tr    ][nt*8 + 2*tc] = make_float2(to_tf32(p0), to_tf32(p1));
            *(float2*)&Ps[lr + tr + 8][nt*8 + 2*tc] = make_float2(to_tf32(p2), to_tf32(p3));
        }
        ls0 += __shfl_xor_sync(0xffffffffu, ls0, 1);
        ls0 += __shfl_xor_sync(0xffffffffu, ls0, 2);
        ls1 += __shfl_xor_sync(0xffffffffu, ls1, 1);
        ls1 += __shfl_xor_sync(0xffffffffu, ls1, 2);
        l0 = l0 * al0 + ls0;
        l1 = l1 * al1 + ls1;

        #pragma unroll
        for (int nt = 0; nt < 16; nt++) {
            o[nt][0] *= al0; o[nt][1] *= al0;
            o[nt][2] *= al1; o[nt][3] *= al1;
        }
        __syncwarp();

        uint32_t pa[4][4];
        #pragma unroll
        for (int ks = 0; ks < 4; ks++) {
            pa[ks][0] = __float_as_uint(Ps[lr + tr    ][ks*8 + tc    ]);
            pa[ks][1] = __float_as_uint(Ps[lr + tr + 8][ks*8 + tc    ]);
            pa[ks][2] = __float_as_uint(Ps[lr + tr    ][ks*8 + tc + 4]);
            pa[ks][3] = __float_as_uint(Ps[lr + tr + 8][ks*8 + tc + 4]);
        }
        #pragma unroll
        for (int nt = 0; nt < 16; nt++) {
            #pragma unroll
            for (int ks = 0; ks < 4; ks++) {
                uint32_t bfr[2];
                bfr[0] = __float_as_uint(Vs[ks*8 + tc    ][nt*8 + tr]);
                bfr[1] = __float_as_uint(Vs[ks*8 + tc + 4][nt*8 + tr]);
                mma_tf32(o[nt], pa[ks], bfr);
            }
        }
        __syncthreads();
    }

    const float iv0 = 1.0f / l0, iv1 = 1.0f / l1;
    const size_t row0 = (size_t)b * S_ + qrow0 + lr + tr;
    float* op0 = g_attn + row0 * HID_ + h*D_ + 2*tc;
    float* op1 = g_attn + (row0 + 8) * HID_ + h*D_ + 2*tc;
    #pragma unroll
    for (int nt = 0; nt < 16; nt++) {
        *(float2*)(op0 + nt*8) = make_float2(o[nt][0]*iv0, o[nt][1]*iv0);
        *(float2*)(op1 + nt*8) = make_float2(o[nt][2]*iv1, o[nt][3]*iv1);
    }
}

// ------------------------------- launch ------------------------------------
extern "C" void kernel_launch(void* const* d_in, const int* in_sizes, int n_in,
                              void* d_out, int out_size)
{
    const float* hidden  = (const float*)d_in[0];
    const float* cosT    = (const float*)d_in[1];
    const float* sinT    = (const float*)d_in[2];
    const float* w_qkv   = (const float*)d_in[3];
    const float* q_ln    = (const float*)d_in[4];
    const float* k_ln    = (const float*)d_in[5];
    const float* w_dense = (const float*)d_in[6];
    float* out = (float*)d_out;

    float *qkv_ptr, *attn_ptr;
    cudaGetSymbolAddress((void**)&qkv_ptr,  g_qkv);
    cudaGetSymbolAddress((void**)&attn_ptr, g_attn);

    // 1) QKV projection
    {
        dim3 grid(QKV_N/128, M_/128);
        gemm_tf32_nt<<<grid, 128>>>(hidden, w_qkv, qkv_ptr, M_, QKV_N, HID_);
    }
    // 2) RMSNorm + RoPE + scatter
    {
        dim3 grid(H_ + 2*HK_, S_, B_);
        norm_rope_kernel<<<grid, 128>>>(qkv_ptr, cosT, sinT, q_ln, k_ln);
    }
    // 3) Flash attention (tf32 mma)
    {
        dim3 grid(S_/64, B_*H_);
        flash_mma_kernel<<<grid, 128>>>();
    }
    // 4) Output projection
    {
        dim3 grid(HID_/128, M_/128);
        gemm_tf32_nt<<<grid, 128>>>(attn_ptr, w_dense, out, M_, HID_, HID_);
    }
}